// round 11
// baseline (speedup 1.0000x reference)
#include <cuda_runtime.h>
#include <cuda_fp16.h>
#include <math.h>
#include <stdint.h>

#define Bb 2
#define Ss 2048
#define Dd 1024
#define Hh 16
#define DK 64
#define FFd 4096
#define ROWS (Bb*Ss)          // 4096
#define NEGV (-1000000000.0f)
typedef __half f16;

// ---------------- scratch ----------------
__device__ __align__(256) float g_qkv[ROWS*3*Dd];   // fused q|k|v fp32
__device__ __align__(256) float g_x1 [ROWS*Dd];
__device__ __align__(256) f16   g_sa_h[ROWS*Dd];    // split of n / o / n2 (sequential reuse)
__device__ __align__(256) f16   g_sa_l[ROWS*Dd];
__device__ __align__(256) f16   g_sf_h[ROWS*FFd];   // split of ff
__device__ __align__(256) f16   g_sf_l[ROWS*FFd];
__device__ __align__(256) f16   g_wt [Dd*FFd];      // transposed fp16 weight [N][K]
__device__ __align__(256) float g_bcat[3*Dd];

__device__ __forceinline__ void split1(float v, f16* h, f16* l, size_t idx) {
    f16 hv = __float2half_rn(v);
    h[idx] = hv;
    l[idx] = __float2half_rn(v - __half2float(hv));
}

// ---------------- weight transpose + fp16 convert: W[K,N] -> Wt[N,K] ----------------
__device__ __forceinline__ void wtcvt_body(const float* __restrict__ W,
                                           f16* __restrict__ t,
                                           int K, int N, int rowOff,
                                           float (*tile)[33]) {
    int kk = blockIdx.y * 32, nn = blockIdx.x * 32;
    int tx = threadIdx.x, ty = threadIdx.y;   // 32 x 8
#pragma unroll
    for (int i = 0; i < 4; i++)
        tile[ty + 8*i][tx] = W[(size_t)(kk + ty + 8*i) * N + nn + tx];
    __syncthreads();
#pragma unroll
    for (int i = 0; i < 4; i++) {
        float v = tile[tx][ty + 8*i];
        t[(size_t)(rowOff + nn + ty + 8*i) * K + kk + tx] = __float2half_rn(v);
    }
}
__global__ void wtcvt_kernel(const float* __restrict__ W, f16* __restrict__ t,
                             int K, int N, int rowOff) {
    __shared__ float tile[32][33];
    wtcvt_body(W, t, K, N, rowOff, tile);
}
__global__ void wtcvt3_kernel(const float* __restrict__ W0, const float* __restrict__ W1,
                              const float* __restrict__ W2, f16* __restrict__ t) {
    __shared__ float tile[32][33];
    const float* W = (blockIdx.z == 0) ? W0 : (blockIdx.z == 1) ? W1 : W2;
    wtcvt_body(W, t, Dd, Dd, blockIdx.z * Dd, tile);
}

// ---------------- bias concat for fused QKV ----------------
__global__ void bcat_kernel(const float* __restrict__ bq, const float* __restrict__ bk,
                            const float* __restrict__ bv, float* __restrict__ o) {
    int i = blockIdx.x * 256 + threadIdx.x;
    if (i < 3*Dd)
        o[i] = (i < Dd) ? bq[i] : ((i < 2*Dd) ? bk[i - Dd] : bv[i - 2*Dd]);
}

// ---------------- layernorm (fused fp16 split output) ----------------
__global__ void ln_split_kernel(const float* __restrict__ x,
                                const float* __restrict__ g,
                                const float* __restrict__ b,
                                f16* __restrict__ oh, f16* __restrict__ ol) {
    int row = blockIdx.x;
    const float* xr = x + (size_t)row * Dd;
    int tid = threadIdx.x;                 // 256 threads
    int lane = tid & 31, warp = tid >> 5;
    __shared__ float red[32];

    float lv[4]; float s = 0.f;
#pragma unroll
    for (int i = 0; i < 4; i++) { lv[i] = xr[tid + i*256]; s += lv[i]; }
#pragma unroll
    for (int off = 16; off; off >>= 1) s += __shfl_down_sync(0xffffffffu, s, off);
    if (lane == 0) red[warp] = s;
    __syncthreads();
    if (tid == 0) { float t = 0.f; for (int w = 0; w < 8; w++) t += red[w]; red[0] = t; }
    __syncthreads();
    float mu = red[0] * (1.0f / Dd);
    __syncthreads();

    float vs = 0.f;
#pragma unroll
    for (int i = 0; i < 4; i++) { float d = lv[i] - mu; vs += d * d; }
#pragma unroll
    for (int off = 16; off; off >>= 1) vs += __shfl_down_sync(0xffffffffu, vs, off);
    if (lane == 0) red[warp] = vs;
    __syncthreads();
    if (tid == 0) { float t = 0.f; for (int w = 0; w < 8; w++) t += red[w]; red[0] = t; }
    __syncthreads();
    float inv = rsqrtf(red[0] * (1.0f / Dd) + 1e-5f);

#pragma unroll
    for (int i = 0; i < 4; i++) {
        int c = tid + i * 256;
        float v = (lv[i] - mu) * inv * g[c] + b[c];
        split1(v, oh, ol, (size_t)row * Dd + c);
    }
}

// ---------------- HMMA fp16 2-term GEMM, BM=128 BN=256, warp tile 64x64 --------------
// C[M,N] = (Ah+Al)[M,K] @ B[N,K]^T + bias (+gelu) (+res)
#define RS 80
#define ARR (128*RS)                // 10240 B per A array
#define BRR (256*RS)                // 20480 B for B
#define STG (2*ARR + BRR)           // 40960 B per stage
#define NSTAGE 3
#define GEMM_SMEM (NSTAGE*STG)      // 122880, 1 CTA/SM

__device__ __forceinline__ void cp16(uint32_t s, const void* g) {
    asm volatile("cp.async.cg.shared.global [%0], [%1], 16;" :: "r"(s), "l"(g) : "memory");
}
#define LDSM4(r, a) asm volatile( \
    "ldmatrix.sync.aligned.m8n8.x4.shared.b16 {%0,%1,%2,%3}, [%4];" \
    : "=r"((r)[0]), "=r"((r)[1]), "=r"((r)[2]), "=r"((r)[3]) : "r"(a))
#define MMA_OP(d, a, b0, b1) asm volatile( \
    "mma.sync.aligned.m16n8k16.row.col.f32.f16.f16.f32 " \
    "{%0,%1,%2,%3}, {%4,%5,%6,%7}, {%8,%9}, {%0,%1,%2,%3};\n" \
    : "+f"((d)[0]), "+f"((d)[1]), "+f"((d)[2]), "+f"((d)[3]) \
    : "r"((a)[0]), "r"((a)[1]), "r"((a)[2]), "r"((a)[3]), "r"(b0), "r"(b1))

template<bool DO_GELU, bool DO_RES, bool OSPLIT>
__global__ __launch_bounds__(256, 1)
void bgemm_mma(const f16* __restrict__ Ah, const f16* __restrict__ Al,
               const f16* __restrict__ B,
               const float* __restrict__ bias, const float* __restrict__ res,
               float* __restrict__ C, f16* __restrict__ Ch, f16* __restrict__ Cl,
               int M, int N, int K) {
    extern __shared__ __align__(128) char smem[];
    const int tid = threadIdx.x, lane = tid & 31, warp = tid >> 5;
    const int wm = warp >> 2, wn = warp & 3;   // 2 x 4, warp tile 64x64
    const int rowBase = blockIdx.y * 128, colBase = blockIdx.x * 256;
    const uint32_t sb = (uint32_t)__cvta_generic_to_shared(smem);
    const int NS = K >> 5;

    auto issue = [&](int s) {
        uint32_t st = sb + (uint32_t)(s % 3) * STG;
        int kk = s << 5;
#pragma unroll
        for (int j = 0; j < 2; j++) {
            int c = tid + (j << 8);
            int r = c >> 2, ke = (c & 3) << 3;
            uint32_t dst = st + r * RS + ((c & 3) << 4);
            size_t ga = (size_t)(rowBase + r) * K + kk + ke;
            cp16(dst,         Ah + ga);
            cp16(dst + ARR,   Al + ga);
        }
#pragma unroll
        for (int j = 0; j < 4; j++) {
            int c = tid + (j << 8);
            int r = c >> 2, ke = (c & 3) << 3;
            uint32_t dst = st + 2*ARR + r * RS + ((c & 3) << 4);
            size_t gb = (size_t)(colBase + r) * K + kk + ke;
            cp16(dst, B + gb);
        }
        asm volatile("cp.async.commit_group;" ::: "memory");
    };

    float acc[4][8][4] = {};   // [mi][n8][4]

    issue(0); issue(1); issue(2);

    for (int s = 0; s < NS; s++) {
        int rem = NS - 1 - s;
        if (rem >= 2)      asm volatile("cp.async.wait_group 2;" ::: "memory");
        else if (rem == 1) asm volatile("cp.async.wait_group 1;" ::: "memory");
        else               asm volatile("cp.async.wait_group 0;" ::: "memory");
        __syncthreads();

        uint32_t st = sb + (uint32_t)(s % 3) * STG;
        uint32_t aBase = st + (wm * 64 + (lane & 15)) * RS + ((lane >> 4) << 4);
        uint32_t bBase = st + 2*ARR + (wn * 64 + (lane & 15)) * RS + ((lane >> 4) << 4);
#pragma unroll
        for (int ks = 0; ks < 2; ks++) {
            uint32_t ko = ks * 32;
            uint32_t ah[4][4], alr[4][4], bh[4][4];
#pragma unroll
            for (int mi = 0; mi < 4; mi++) {
                LDSM4(ah[mi],  aBase + mi * (16*RS) + ko);
                LDSM4(alr[mi], aBase + ARR + mi * (16*RS) + ko);
            }
#pragma unroll
            for (int nb = 0; nb < 4; nb++)
                LDSM4(bh[nb], bBase + nb * (16*RS) + ko);
#pragma unroll
            for (int mi = 0; mi < 4; mi++)
#pragma unroll
                for (int nb = 0; nb < 4; nb++)
#pragma unroll
                    for (int g = 0; g < 2; g++) {
                        float* d = acc[mi][nb*2 + g];
                        MMA_OP(d, ah[mi],  bh[nb][g], bh[nb][g+2]);
                        MMA_OP(d, alr[mi], bh[nb][g], bh[nb][g+2]);
                    }
        }
        __syncthreads();
        if (s + 3 < NS) issue(s + 3);
    }

    // ---- epilogue ----
#pragma unroll
    for (int mi = 0; mi < 4; mi++) {
        int r0 = rowBase + wm * 64 + mi * 16 + (lane >> 2);
#pragma unroll
        for (int n8 = 0; n8 < 8; n8++) {
            int c = colBase + wn * 64 + (n8 >> 1) * 16 + (n8 & 1) * 8 + (lane & 3) * 2;
            float* d = acc[mi][n8];
            float b0 = bias[c], b1 = bias[c + 1];
#pragma unroll
            for (int p = 0; p < 2; p++) {
                int r = r0 + p * 8;
                float v0 = d[p*2]     + b0;
                float v1 = d[p*2 + 1] + b1;
                if (DO_GELU) {
                    v0 = 0.5f * v0 * (1.0f + erff(v0 * 0.70710678118654752f));
                    v1 = 0.5f * v1 * (1.0f + erff(v1 * 0.70710678118654752f));
                }
                if (DO_RES) {
                    float2 rr = *(const float2*)(res + (size_t)r * N + c);
                    v0 += rr.x; v1 += rr.y;
                }
                if (OSPLIT) {
                    f16 h0 = __float2half_rn(v0), h1 = __float2half_rn(v1);
                    f16 l0 = __float2half_rn(v0 - __half2float(h0));
                    f16 l1 = __float2half_rn(v1 - __half2float(h1));
                    uint32_t hp = ((uint32_t)*(uint16_t*)&h1 << 16) | *(uint16_t*)&h0;
                    uint32_t lp = ((uint32_t)*(uint16_t*)&l1 << 16) | *(uint16_t*)&l0;
                    *(uint32_t*)(Ch + (size_t)r * N + c) = hp;
                    *(uint32_t*)(Cl + (size_t)r * N + c) = lp;
                } else {
                    *(float2*)(C + (size_t)r * N + c) = make_float2(v0, v1);
                }
            }
        }
    }
}

// ---------------- query-tile flash sparse attention ----------------
#define KST 68
#define PST 130
#define ATT_SMEM ((2*128*KST + 128*PST) * 4)   // 136192 B

__global__ __launch_bounds__(256)
void attn2_kernel(const float* __restrict__ qkv, const int* __restrict__ mask,
                  f16* __restrict__ oh, f16* __restrict__ ol) {
    extern __shared__ float sm[];
    float* Ks = sm;
    float* Vs = sm + 128*KST;
    float* Ps = sm + 2*128*KST;

    const int qb = blockIdx.x, h = blockIdx.y, b = blockIdx.z;
    const int tid = threadIdx.x;
    const int qi = tid >> 1, half = tid & 1;
    const int i = qb * 128 + qi;
    const float scale = 0.125f;
    const int* mrow = mask + (size_t)i * Ss;

    float qreg[64];
    {
        const float* qptr = qkv + ((size_t)b * Ss + i) * (3*Dd) + h * DK;
#pragma unroll
        for (int d4 = 0; d4 < 16; d4++) {
            float4 v = *(const float4*)(qptr + 4*d4);
            qreg[4*d4] = v.x; qreg[4*d4+1] = v.y; qreg[4*d4+2] = v.z; qreg[4*d4+3] = v.w;
        }
    }

    float m = -3.0e38f, l = 0.f;
    float o[32];
#pragma unroll
    for (int d = 0; d < 32; d++) o[d] = 0.f;

    for (int mm = 2; mm <= qb; mm++) {
        int j = i - 128 * mm;
        const float* kr = qkv + ((size_t)b * Ss + j) * (3*Dd) + Dd + h * DK + half * 32;
        float s0 = 0, s1 = 0, s2 = 0, s3 = 0;
#pragma unroll
        for (int d4 = 0; d4 < 8; d4++) {
            float4 kv = *(const float4*)(kr + 4*d4);
            s0 += qreg[half*32 + 4*d4]     * kv.x;
            s1 += qreg[half*32 + 4*d4 + 1] * kv.y;
            s2 += qreg[half*32 + 4*d4 + 2] * kv.z;
            s3 += qreg[half*32 + 4*d4 + 3] * kv.w;
        }
        float sc = (s0 + s1) + (s2 + s3);
        sc += __shfl_xor_sync(0xffffffffu, sc, 1);
        sc *= scale;
        if (mrow[j] == 0) sc = NEGV;

        float mn = fmaxf(m, sc);
        float corr = __expf(m - mn);
        float p = __expf(sc - mn);
        l = l * corr + (half ? 0.f : p);
        m = mn;
        const float* vr = qkv + ((size_t)b * Ss + j) * (3*Dd) + 2*Dd + h * DK + half * 32;
#pragma unroll
        for (int d4 = 0; d4 < 8; d4++) {
            float4 vv = *(const float4*)(vr + 4*d4);
            o[4*d4]   = o[4*d4]   * corr + p * vv.x;
            o[4*d4+1] = o[4*d4+1] * corr + p * vv.y;
            o[4*d4+2] = o[4*d4+2] * corr + p * vv.z;
            o[4*d4+3] = o[4*d4+3] * corr + p * vv.w;
        }
    }

    int t0 = (qb > 0) ? qb - 1 : 0;
    for (int t = t0; t <= qb; t++) {
        __syncthreads();
        const float* gk = qkv + ((size_t)b * Ss + t*128) * (3*Dd) + Dd + h * DK;
        const float* gv = gk + Dd;
        for (int idx = tid; idx < 8192; idx += 256) {
            int r = idx >> 6, d = idx & 63;
            Ks[r*KST + d] = gk[(size_t)r * (3*Dd) + d];
            Vs[r*KST + d] = gv[(size_t)r * (3*Dd) + d];
        }
        __syncthreads();

        float tmax = -3.0e38f;
        int jbase = t * 128;
        for (int c = 0; c < 64; c++) {
            int kj = half*64 + c;
            bool allowed = (t == qb) ? (kj <= qi) : (kj >= qi);
            float sc = NEGV;
            if (allowed && mrow[jbase + kj] != 0) {
                const float* kr = &Ks[kj*KST];
                float s0 = 0, s1 = 0, s2 = 0, s3 = 0;
#pragma unroll
                for (int d4 = 0; d4 < 16; d4++) {
                    float4 kv = *(const float4*)(kr + 4*d4);
                    s0 += qreg[4*d4]   * kv.x;
                    s1 += qreg[4*d4+1] * kv.y;
                    s2 += qreg[4*d4+2] * kv.z;
                    s3 += qreg[4*d4+3] * kv.w;
                }
                sc = ((s0 + s1) + (s2 + s3)) * scale;
            }
            Ps[qi*PST + kj] = sc;
            tmax = fmaxf(tmax, sc);
        }
        tmax = fmaxf(tmax, __shfl_xor_sync(0xffffffffu, tmax, 1));
        float mn = fmaxf(m, tmax);
        float corr = __expf(m - mn);
        float lsum = 0.f;
        for (int c = 0; c < 64; c++) {
            int kj = half*64 + c;
            float p = __expf(Ps[qi*PST + kj] - mn);
            Ps[qi*PST + kj] = p;
            lsum += p;
        }
        l = l * corr + lsum;
        m = mn;
#pragma unroll
        for (int d = 0; d < 32; d++) o[d] *= corr;
        __syncthreads();

        for (int kj = 0; kj < 128; kj++) {
            float p = Ps[qi*PST + kj];
            if (p != 0.f) {
                const float* vr = &Vs[kj*KST + half*32];
#pragma unroll
                for (int d4 = 0; d4 < 8; d4++) {
                    float4 vv = *(const float4*)(vr + 4*d4);
                    o[4*d4]   += p * vv.x;
                    o[4*d4+1] += p * vv.y;
                    o[4*d4+2] += p * vv.z;
                    o[4*d4+3] += p * vv.w;
                }
            }
        }
    }

    float lt = l + __shfl_xor_sync(0xffffffffu, l, 1);
    float inv = 1.0f / lt;
    size_t obase = ((size_t)b * Ss + i) * Dd + h * DK + half * 32;
#pragma unroll
    for (int d = 0; d < 32; d++) {
        float val = o[d] * inv;
        f16 hv = __float2half_rn(val);
        oh[obase + d] = hv;
        ol[obase + d] = __float2half_rn(val - __half2float(hv));
    }
}

// ---------------- launch ----------------
extern "C" void kernel_launch(void* const* d_in, const int* in_sizes, int n_in,
                              void* d_out, int out_size) {
    const float* x   = (const float*)d_in[0];
    const int*   msk = (const int*)  d_in[1];
    const float* Wq  = (const float*)d_in[2],  *bq  = (const float*)d_in[3];
    const float* Wk  = (const float*)d_in[4],  *bk  = (const float*)d_in[5];
    const float* Wv  = (const float*)d_in[6],  *bv  = (const float*)d_in[7];
    const float* Wo  = (const float*)d_in[8],  *bo  = (const float*)d_in[9];
    const float* W1  = (const float*)d_in[10], *bf1 = (const float*)d_in[11];
    const float* W2  = (const float*)d_in[12], *bf2 = (const float*)d_in[13];
    const float* g1  = (const float*)d_in[14], *bl1 = (const float*)d_in[15];
    const float* g2  = (const float*)d_in[16], *bl2 = (const float*)d_in[17];
    float* out = (float*)d_out;

    float *qkv_, *x1_, *bcat_;
    f16 *sah, *sal, *sfh, *sfl, *wt;
    cudaGetSymbolAddress((void**)&qkv_, g_qkv);
    cudaGetSymbolAddress((void**)&x1_,  g_x1);
    cudaGetSymbolAddress((void**)&bcat_,g_bcat);
    cudaGetSymbolAddress((void**)&sah,  g_sa_h);
    cudaGetSymbolAddress((void**)&sal,  g_sa_l);
    cudaGetSymbolAddress((void**)&sfh,  g_sf_h);
    cudaGetSymbolAddress((void**)&sfl,  g_sf_l);
    cudaGetSymbolAddress((void**)&wt,   g_wt);

    cudaFuncSetAttribute(bgemm_mma<false, false, false>,
                         cudaFuncAttributeMaxDynamicSharedMemorySize, GEMM_SMEM);
    cudaFuncSetAttribute(bgemm_mma<false, true, false>,
                         cudaFuncAttributeMaxDynamicSharedMemorySize, GEMM_SMEM);
    cudaFuncSetAttribute(bgemm_mma<true, false, true>,
                         cudaFuncAttributeMaxDynamicSharedMemorySize, GEMM_SMEM);
    cudaFuncSetAttribute(attn2_kernel,
                         cudaFuncAttributeMaxDynamicSharedMemorySize, ATT_SMEM);

    dim3 wblk(32, 8);

    // pre-LN 1 -> split(n)
    ln_split_kernel<<<ROWS, 256>>>(x, g1, bl1, sah, sal);

    // fused QKV: Wt = [3072][1024]
    bcat_kernel<<<12, 256>>>(bq, bk, bv, bcat_);
    wtcvt3_kernel<<<dim3(Dd/32, Dd/32, 3), wblk>>>(Wq, Wk, Wv, wt);
    bgemm_mma<false, false, false><<<dim3(3*Dd/256, ROWS/128), 256, GEMM_SMEM>>>(
        sah, sal, wt, bcat_, nullptr, qkv_, nullptr, nullptr, ROWS, 3*Dd, Dd);

    // sparse flash attention -> split(o)
    attn2_kernel<<<dim3(Ss/128, Hh, Bb), 256, ATT_SMEM>>>(qkv_, msk, sah, sal);

    // output projection + residual -> x1
    wtcvt_kernel<<<dim3(Dd/32, Dd/32), wblk>>>(Wo, wt, Dd, Dd, 0);
    bgemm_mma<false, true, false><<<dim3(Dd/256, ROWS/128), 256, GEMM_SMEM>>>(
        sah, sal, wt, bo, x, x1_, nullptr, nullptr, ROWS, Dd, Dd);

    // pre-LN 2 -> split(n2)
    ln_split_kernel<<<ROWS, 256>>>(x1_, g2, bl2, sah, sal);

    // FFN up + GELU -> split(ff)
    wtcvt_kernel<<<dim3(FFd/32, Dd/32), wblk>>>(W1, wt, Dd, FFd, 0);
    bgemm_mma<true, false, true><<<dim3(FFd/256, ROWS/128), 256, GEMM_SMEM>>>(
        sah, sal, wt, bf1, nullptr, nullptr, sfh, sfl, ROWS, FFd, Dd);

    // FFN down + residual -> out
    wtcvt_kernel<<<dim3(Dd/32, FFd/32), wblk>>>(W2, wt, FFd, Dd, 0);
    bgemm_mma<false, true, false><<<dim3(Dd/256, ROWS/128), 256, GEMM_SMEM>>>(
        sfh, sfl, wt, bf2, x1_, out, nullptr, nullptr, ROWS, Dd, FFd);
}

// round 12
// speedup vs baseline: 1.5631x; 1.5631x over previous
#include <cuda_runtime.h>
#include <cuda_fp16.h>
#include <math.h>
#include <stdint.h>

#define Bb 2
#define Ss 2048
#define Dd 1024
#define Hh 16
#define DK 64
#define FFd 4096
#define ROWS (Bb*Ss)          // 4096
#define NEGV (-1000000000.0f)
typedef __half f16;

// ---------------- scratch ----------------
__device__ __align__(256) float g_qkv[ROWS*3*Dd];   // fused q|k|v fp32
__device__ __align__(256) float g_x1 [ROWS*Dd];
__device__ __align__(256) f16   g_sa_h[ROWS*Dd];    // split of n / o / n2 (sequential reuse)
__device__ __align__(256) f16   g_sa_l[ROWS*Dd];
__device__ __align__(256) f16   g_sf_h[ROWS*FFd];   // split of ff
__device__ __align__(256) f16   g_sf_l[ROWS*FFd];
__device__ __align__(256) f16   g_wt [Dd*FFd];      // transposed fp16 weight [N][K]
__device__ __align__(256) float g_bcat[3*Dd];

__device__ __forceinline__ void split1(float v, f16* h, f16* l, size_t idx) {
    f16 hv = __float2half_rn(v);
    h[idx] = hv;
    l[idx] = __float2half_rn(v - __half2float(hv));
}

// ---------------- weight transpose + fp16 convert: W[K,N] -> Wt[N,K] ----------------
__device__ __forceinline__ void wtcvt_body(const float* __restrict__ W,
                                           f16* __restrict__ t,
                                           int K, int N, int rowOff,
                                           float (*tile)[33]) {
    int kk = blockIdx.y * 32, nn = blockIdx.x * 32;
    int tx = threadIdx.x, ty = threadIdx.y;   // 32 x 8
#pragma unroll
    for (int i = 0; i < 4; i++)
        tile[ty + 8*i][tx] = W[(size_t)(kk + ty + 8*i) * N + nn + tx];
    __syncthreads();
#pragma unroll
    for (int i = 0; i < 4; i++) {
        float v = tile[tx][ty + 8*i];
        t[(size_t)(rowOff + nn + ty + 8*i) * K + kk + tx] = __float2half_rn(v);
    }
}
__global__ void wtcvt_kernel(const float* __restrict__ W, f16* __restrict__ t,
                             int K, int N, int rowOff) {
    __shared__ float tile[32][33];
    wtcvt_body(W, t, K, N, rowOff, tile);
}
__global__ void wtcvt3_kernel(const float* __restrict__ W0, const float* __restrict__ W1,
                              const float* __restrict__ W2, f16* __restrict__ t) {
    __shared__ float tile[32][33];
    const float* W = (blockIdx.z == 0) ? W0 : (blockIdx.z == 1) ? W1 : W2;
    wtcvt_body(W, t, Dd, Dd, blockIdx.z * Dd, tile);
}

// ---------------- bias concat for fused QKV ----------------
__global__ void bcat_kernel(const float* __restrict__ bq, const float* __restrict__ bk,
                            const float* __restrict__ bv, float* __restrict__ o) {
    int i = blockIdx.x * 256 + threadIdx.x;
    if (i < 3*Dd)
        o[i] = (i < Dd) ? bq[i] : ((i < 2*Dd) ? bk[i - Dd] : bv[i - 2*Dd]);
}

// ---------------- layernorm (fused fp16 split output) ----------------
__global__ void ln_split_kernel(const float* __restrict__ x,
                                const float* __restrict__ g,
                                const float* __restrict__ b,
                                f16* __restrict__ oh, f16* __restrict__ ol) {
    int row = blockIdx.x;
    const float* xr = x + (size_t)row * Dd;
    int tid = threadIdx.x;                 // 256 threads
    int lane = tid & 31, warp = tid >> 5;
    __shared__ float red[32];

    float lv[4]; float s = 0.f;
#pragma unroll
    for (int i = 0; i < 4; i++) { lv[i] = xr[tid + i*256]; s += lv[i]; }
#pragma unroll
    for (int off = 16; off; off >>= 1) s += __shfl_down_sync(0xffffffffu, s, off);
    if (lane == 0) red[warp] = s;
    __syncthreads();
    if (tid == 0) { float t = 0.f; for (int w = 0; w < 8; w++) t += red[w]; red[0] = t; }
    __syncthreads();
    float mu = red[0] * (1.0f / Dd);
    __syncthreads();

    float vs = 0.f;
#pragma unroll
    for (int i = 0; i < 4; i++) { float d = lv[i] - mu; vs += d * d; }
#pragma unroll
    for (int off = 16; off; off >>= 1) vs += __shfl_down_sync(0xffffffffu, vs, off);
    if (lane == 0) red[warp] = vs;
    __syncthreads();
    if (tid == 0) { float t = 0.f; for (int w = 0; w < 8; w++) t += red[w]; red[0] = t; }
    __syncthreads();
    float inv = rsqrtf(red[0] * (1.0f / Dd) + 1e-5f);

#pragma unroll
    for (int i = 0; i < 4; i++) {
        int c = tid + i * 256;
        float v = (lv[i] - mu) * inv * g[c] + b[c];
        split1(v, oh, ol, (size_t)row * Dd + c);
    }
}

// ---------------- HMMA fp16 2-term GEMM: BM=BN=128, 4 warps of 64x64, 2 CTA/SM ------
// C[M,N] = (Ah+Al)[M,K] @ B[N,K]^T + bias (+gelu) (+res)
#define RS 80
#define ARR (128*RS)                // 10240 B per array
#define STG (3*ARR)                 // 30720 B per stage (Ah|Al|B)
#define NSTAGE 3
#define GEMM_SMEM (NSTAGE*STG)      // 92160 -> 2 CTAs/SM (184320 < 228KB)

__device__ __forceinline__ void cp16(uint32_t s, const void* g) {
    asm volatile("cp.async.cg.shared.global [%0], [%1], 16;" :: "r"(s), "l"(g) : "memory");
}
#define LDSM4(r, a) asm volatile( \
    "ldmatrix.sync.aligned.m8n8.x4.shared.b16 {%0,%1,%2,%3}, [%4];" \
    : "=r"((r)[0]), "=r"((r)[1]), "=r"((r)[2]), "=r"((r)[3]) : "r"(a))
#define MMA_OP(d, a, b0, b1) asm volatile( \
    "mma.sync.aligned.m16n8k16.row.col.f32.f16.f16.f32 " \
    "{%0,%1,%2,%3}, {%4,%5,%6,%7}, {%8,%9}, {%0,%1,%2,%3};\n" \
    : "+f"((d)[0]), "+f"((d)[1]), "+f"((d)[2]), "+f"((d)[3]) \
    : "r"((a)[0]), "r"((a)[1]), "r"((a)[2]), "r"((a)[3]), "r"(b0), "r"(b1))

template<bool DO_GELU, bool DO_RES, bool OSPLIT>
__global__ __launch_bounds__(128, 2)
void bgemm_mma(const f16* __restrict__ Ah, const f16* __restrict__ Al,
               const f16* __restrict__ B,
               const float* __restrict__ bias, const float* __restrict__ res,
               float* __restrict__ C, f16* __restrict__ Ch, f16* __restrict__ Cl,
               int M, int N, int K) {
    extern __shared__ __align__(128) char smem[];
    const int tid = threadIdx.x, lane = tid & 31, warp = tid >> 5;
    const int wm = warp >> 1, wn = warp & 1;   // 2 x 2, warp tile 64x64
    const int rowBase = blockIdx.y * 128, colBase = blockIdx.x * 128;
    const uint32_t sb = (uint32_t)__cvta_generic_to_shared(smem);
    const int NS = K >> 5;

    auto issue = [&](int s) {
        uint32_t st = sb + (uint32_t)(s % 3) * STG;
        int kk = s << 5;
#pragma unroll
        for (int j = 0; j < 4; j++) {
            int c = tid + (j << 7);               // 0..511
            int r = c >> 2, ke = (c & 3) << 3;
            uint32_t dst = st + r * RS + ((c & 3) << 4);
            size_t ga = (size_t)(rowBase + r) * K + kk + ke;
            size_t gb = (size_t)(colBase + r) * K + kk + ke;
            cp16(dst,           Ah + ga);
            cp16(dst +   ARR,   Al + ga);
            cp16(dst + 2*ARR,   B  + gb);
        }
        asm volatile("cp.async.commit_group;" ::: "memory");
    };

    float acc[4][8][4] = {};   // [mi][n8][4]

    issue(0); issue(1); issue(2);

    for (int s = 0; s < NS; s++) {
        int rem = NS - 1 - s;
        if (rem >= 2)      asm volatile("cp.async.wait_group 2;" ::: "memory");
        else if (rem == 1) asm volatile("cp.async.wait_group 1;" ::: "memory");
        else               asm volatile("cp.async.wait_group 0;" ::: "memory");
        __syncthreads();

        uint32_t st = sb + (uint32_t)(s % 3) * STG;
        uint32_t aBase = st + (wm * 64 + (lane & 15)) * RS + ((lane >> 4) << 4);
        uint32_t bBase = st + 2*ARR + (wn * 64 + (lane & 15)) * RS + ((lane >> 4) << 4);
#pragma unroll
        for (int ks = 0; ks < 2; ks++) {
            uint32_t ko = ks * 32;
            uint32_t ah[4][4], alr[4][4], bh[4][4];
#pragma unroll
            for (int mi = 0; mi < 4; mi++) {
                LDSM4(ah[mi],  aBase + mi * (16*RS) + ko);
                LDSM4(alr[mi], aBase + ARR + mi * (16*RS) + ko);
            }
#pragma unroll
            for (int nb = 0; nb < 4; nb++)
                LDSM4(bh[nb], bBase + nb * (16*RS) + ko);
#pragma unroll
            for (int mi = 0; mi < 4; mi++)
#pragma unroll
                for (int nb = 0; nb < 4; nb++)
#pragma unroll
                    for (int g = 0; g < 2; g++) {
                        float* d = acc[mi][nb*2 + g];
                        MMA_OP(d, ah[mi],  bh[nb][g], bh[nb][g+2]);
                        MMA_OP(d, alr[mi], bh[nb][g], bh[nb][g+2]);
                    }
        }
        __syncthreads();
        if (s + 3 < NS) issue(s + 3);
    }

    // ---- epilogue ----
#pragma unroll
    for (int mi = 0; mi < 4; mi++) {
        int r0 = rowBase + wm * 64 + mi * 16 + (lane >> 2);
#pragma unroll
        for (int n8 = 0; n8 < 8; n8++) {
            int c = colBase + wn * 64 + (n8 >> 1) * 16 + (n8 & 1) * 8 + (lane & 3) * 2;
            float* d = acc[mi][n8];
            float b0 = bias[c], b1 = bias[c + 1];
#pragma unroll
            for (int p = 0; p < 2; p++) {
                int r = r0 + p * 8;
                float v0 = d[p*2]     + b0;
                float v1 = d[p*2 + 1] + b1;
                if (DO_GELU) {
                    v0 = 0.5f * v0 * (1.0f + erff(v0 * 0.70710678118654752f));
                    v1 = 0.5f * v1 * (1.0f + erff(v1 * 0.70710678118654752f));
                }
                if (DO_RES) {
                    float2 rr = *(const float2*)(res + (size_t)r * N + c);
                    v0 += rr.x; v1 += rr.y;
                }
                if (OSPLIT) {
                    f16 h0 = __float2half_rn(v0), h1 = __float2half_rn(v1);
                    f16 l0 = __float2half_rn(v0 - __half2float(h0));
                    f16 l1 = __float2half_rn(v1 - __half2float(h1));
                    uint32_t hp = ((uint32_t)*(uint16_t*)&h1 << 16) | *(uint16_t*)&h0;
                    uint32_t lp = ((uint32_t)*(uint16_t*)&l1 << 16) | *(uint16_t*)&l0;
                    *(uint32_t*)(Ch + (size_t)r * N + c) = hp;
                    *(uint32_t*)(Cl + (size_t)r * N + c) = lp;
                } else {
                    *(float2*)(C + (size_t)r * N + c) = make_float2(v0, v1);
                }
            }
        }
    }
}

// ---------------- query-tile flash sparse attention ----------------
#define KST 68
#define PST 130
#define ATT_SMEM ((2*128*KST + 128*PST) * 4)   // 136192 B

__global__ __launch_bounds__(256)
void attn2_kernel(const float* __restrict__ qkv, const int* __restrict__ mask,
                  f16* __restrict__ oh, f16* __restrict__ ol) {
    extern __shared__ float sm[];
    float* Ks = sm;
    float* Vs = sm + 128*KST;
    float* Ps = sm + 2*128*KST;

    const int qb = blockIdx.x, h = blockIdx.y, b = blockIdx.z;
    const int tid = threadIdx.x;
    const int qi = tid >> 1, half = tid & 1;
    const int i = qb * 128 + qi;
    const float scale = 0.125f;
    const int* mrow = mask + (size_t)i * Ss;

    float qreg[64];
    {
        const float* qptr = qkv + ((size_t)b * Ss + i) * (3*Dd) + h * DK;
#pragma unroll
        for (int d4 = 0; d4 < 16; d4++) {
            float4 v = *(const float4*)(qptr + 4*d4);
            qreg[4*d4] = v.x; qreg[4*d4+1] = v.y; qreg[4*d4+2] = v.z; qreg[4*d4+3] = v.w;
        }
    }

    float m = -3.0e38f, l = 0.f;
    float o[32];
#pragma unroll
    for (int d = 0; d < 32; d++) o[d] = 0.f;

    for (int mm = 2; mm <= qb; mm++) {
        int j = i - 128 * mm;
        const float* kr = qkv + ((size_t)b * Ss + j) * (3*Dd) + Dd + h * DK + half * 32;
        float s0 = 0, s1 = 0, s2 = 0, s3 = 0;
#pragma unroll
        for (int d4 = 0; d4 < 8; d4++) {
            float4 kv = *(const float4*)(kr + 4*d4);
            s0 += qreg[half*32 + 4*d4]     * kv.x;
            s1 += qreg[half*32 + 4*d4 + 1] * kv.y;
            s2 += qreg[half*32 + 4*d4 + 2] * kv.z;
            s3 += qreg[half*32 + 4*d4 + 3] * kv.w;
        }
        float sc = (s0 + s1) + (s2 + s3);
        sc += __shfl_xor_sync(0xffffffffu, sc, 1);
        sc *= scale;
        if (mrow[j] == 0) sc = NEGV;

        float mn = fmaxf(m, sc);
        float corr = __expf(m - mn);
        float p = __expf(sc - mn);
        l = l * corr + (half ? 0.f : p);
        m = mn;
        const float* vr = qkv + ((size_t)b * Ss + j) * (3*Dd) + 2*Dd + h * DK + half * 32;
#pragma unroll
        for (int d4 = 0; d4 < 8; d4++) {
            float4 vv = *(const float4*)(vr + 4*d4);
            o[4*d4]   = o[4*d4]   * corr + p * vv.x;
            o[4*d4+1] = o[4*d4+1] * corr + p * vv.y;
            o[4*d4+2] = o[4*d4+2] * corr + p * vv.z;
            o[4*d4+3] = o[4*d4+3] * corr + p * vv.w;
        }
    }

    int t0 = (qb > 0) ? qb - 1 : 0;
    for (int t = t0; t <= qb; t++) {
        __syncthreads();
        const float* gk = qkv + ((size_t)b * Ss + t*128) * (3*Dd) + Dd + h * DK;
        const float* gv = gk + Dd;
        for (int idx = tid; idx < 8192; idx += 256) {
            int r = idx >> 6, d = idx & 63;
            Ks[r*KST + d] = gk[(size_t)r * (3*Dd) + d];
            Vs[r*KST + d] = gv[(size_t)r * (3*Dd) + d];
        }
        __syncthreads();

        float tmax = -3.0e38f;
        int jbase = t * 128;
        for (int c = 0; c < 64; c++) {
            int kj = half*64 + c;
            bool allowed = (t == qb) ? (kj <= qi) : (kj >= qi);
            float sc = NEGV;
            if (allowed && mrow[jbase + kj] != 0) {
                const float* kr = &Ks[kj*KST];
                float s0 = 0, s1 = 0, s2 = 0, s3 = 0;
#pragma unroll
                for (int d4 = 0; d4 < 16; d4++) {
                    float4 kv = *(const float4*)(kr + 4*d4);
                    s0 += qreg[4*d4]   * kv.x;
                    s1 += qreg[4*d4+1] * kv.y;
                    s2 += qreg[4*d4+2] * kv.z;
                    s3 += qreg[4*d4+3] * kv.w;
                }
                sc = ((s0 + s1) + (s2 + s3)) * scale;
            }
            Ps[qi*PST + kj] = sc;
            tmax = fmaxf(tmax, sc);
        }
        tmax = fmaxf(tmax, __shfl_xor_sync(0xffffffffu, tmax, 1));
        float mn = fmaxf(m, tmax);
        float corr = __expf(m - mn);
        float lsum = 0.f;
        for (int c = 0; c < 64; c++) {
            int kj = half*64 + c;
            float p = __expf(Ps[qi*PST + kj] - mn);
            Ps[qi*PST + kj] = p;
            lsum += p;
        }
        l = l * corr + lsum;
        m = mn;
#pragma unroll
        for (int d = 0; d < 32; d++) o[d] *= corr;
        __syncthreads();

        for (int kj = 0; kj < 128; kj++) {
            float p = Ps[qi*PST + kj];
            if (p != 0.f) {
                const float* vr = &Vs[kj*KST + half*32];
#pragma unroll
                for (int d4 = 0; d4 < 8; d4++) {
                    float4 vv = *(const float4*)(vr + 4*d4);
                    o[4*d4]   += p * vv.x;
                    o[4*d4+1] += p * vv.y;
                    o[4*d4+2] += p * vv.z;
                    o[4*d4+3] += p * vv.w;
                }
            }
        }
    }

    float lt = l + __shfl_xor_sync(0xffffffffu, l, 1);
    float inv = 1.0f / lt;
    size_t obase = ((size_t)b * Ss + i) * Dd + h * DK + half * 32;
#pragma unroll
    for (int d = 0; d < 32; d++) {
        float val = o[d] * inv;
        f16 hv = __float2half_rn(val);
        oh[obase + d] = hv;
        ol[obase + d] = __float2half_rn(val - __half2float(hv));
    }
}

// ---------------- launch ----------------
extern "C" void kernel_launch(void* const* d_in, const int* in_sizes, int n_in,
                              void* d_out, int out_size) {
    const float* x   = (const float*)d_in[0];
    const int*   msk = (const int*)  d_in[1];
    const float* Wq  = (const float*)d_in[2],  *bq  = (const float*)d_in[3];
    const float* Wk  = (const float*)d_in[4],  *bk  = (const float*)d_in[5];
    const float* Wv  = (const float*)d_in[6],  *bv  = (const float*)d_in[7];
    const float* Wo  = (const float*)d_in[8],  *bo  = (const float*)d_in[9];
    const float* W1  = (const float*)d_in[10], *bf1 = (const float*)d_in[11];
    const float* W2  = (const float*)d_in[12], *bf2 = (const float*)d_in[13];
    const float* g1  = (const float*)d_in[14], *bl1 = (const float*)d_in[15];
    const float* g2  = (const float*)d_in[16], *bl2 = (const float*)d_in[17];
    float* out = (float*)d_out;

    float *qkv_, *x1_, *bcat_;
    f16 *sah, *sal, *sfh, *sfl, *wt;
    cudaGetSymbolAddress((void**)&qkv_, g_qkv);
    cudaGetSymbolAddress((void**)&x1_,  g_x1);
    cudaGetSymbolAddress((void**)&bcat_,g_bcat);
    cudaGetSymbolAddress((void**)&sah,  g_sa_h);
    cudaGetSymbolAddress((void**)&sal,  g_sa_l);
    cudaGetSymbolAddress((void**)&sfh,  g_sf_h);
    cudaGetSymbolAddress((void**)&sfl,  g_sf_l);
    cudaGetSymbolAddress((void**)&wt,   g_wt);

    cudaFuncSetAttribute(bgemm_mma<false, false, false>,
                         cudaFuncAttributeMaxDynamicSharedMemorySize, GEMM_SMEM);
    cudaFuncSetAttribute(bgemm_mma<false, true, false>,
                         cudaFuncAttributeMaxDynamicSharedMemorySize, GEMM_SMEM);
    cudaFuncSetAttribute(bgemm_mma<true, false, true>,
                         cudaFuncAttributeMaxDynamicSharedMemorySize, GEMM_SMEM);
    cudaFuncSetAttribute(attn2_kernel,
                         cudaFuncAttributeMaxDynamicSharedMemorySize, ATT_SMEM);

    dim3 wblk(32, 8);

    // pre-LN 1 -> split(n)
    ln_split_kernel<<<ROWS, 256>>>(x, g1, bl1, sah, sal);

    // fused QKV: Wt = [3072][1024]
    bcat_kernel<<<12, 256>>>(bq, bk, bv, bcat_);
    wtcvt3_kernel<<<dim3(Dd/32, Dd/32, 3), wblk>>>(Wq, Wk, Wv, wt);
    bgemm_mma<false, false, false><<<dim3(3*Dd/128, ROWS/128), 128, GEMM_SMEM>>>(
        sah, sal, wt, bcat_, nullptr, qkv_, nullptr, nullptr, ROWS, 3*Dd, Dd);

    // sparse flash attention -> split(o)
    attn2_kernel<<<dim3(Ss/128, Hh, Bb), 256, ATT_SMEM>>>(qkv_, msk, sah, sal);

    // output projection + residual -> x1
    wtcvt_kernel<<<dim3(Dd/32, Dd/32), wblk>>>(Wo, wt, Dd, Dd, 0);
    bgemm_mma<false, true, false><<<dim3(Dd/128, ROWS/128), 128, GEMM_SMEM>>>(
        sah, sal, wt, bo, x, x1_, nullptr, nullptr, ROWS, Dd, Dd);

    // pre-LN 2 -> split(n2)
    ln_split_kernel<<<ROWS, 256>>>(x1_, g2, bl2, sah, sal);

    // FFN up + GELU -> split(ff)
    wtcvt_kernel<<<dim3(FFd/32, Dd/32), wblk>>>(W1, wt, Dd, FFd, 0);
    bgemm_mma<true, false, true><<<dim3(FFd/128, ROWS/128), 128, GEMM_SMEM>>>(
        sah, sal, wt, bf1, nullptr, nullptr, sfh, sfl, ROWS, FFd, Dd);

    // FFN down + residual -> out
    wtcvt_kernel<<<dim3(Dd/32, FFd/32), wblk>>>(W2, wt, FFd, Dd, 0);
    bgemm_mma<false, true, false><<<dim3(Dd/128, ROWS/128), 128, GEMM_SMEM>>>(
        sfh, sfl, wt, bf2, x1_, out, nullptr, nullptr, ROWS, Dd, FFd);
}

// round 15
// speedup vs baseline: 1.8162x; 1.1619x over previous
#include <cuda_runtime.h>
#include <cuda_fp16.h>
#include <math.h>
#include <stdint.h>

#define Bb 2
#define Ss 2048
#define Dd 1024
#define Hh 16
#define DK 64
#define FFd 4096
#define ROWS (Bb*Ss)          // 4096
#define NEGV (-1000000000.0f)
typedef __half f16;

// ---------------- scratch ----------------
__device__ __align__(256) float g_qkv[ROWS*3*Dd];   // fused q|k|v fp32
__device__ __align__(256) float g_x1 [ROWS*Dd];
__device__ __align__(256) f16   g_sa_h[ROWS*Dd];    // hi of n / o / n2 (sequential reuse)
__device__ __align__(256) f16   g_sa_l[ROWS*Dd];    // lo of n / n2
__device__ __align__(256) f16   g_sf_h[ROWS*FFd];   // ff (hi only)
__device__ __align__(256) f16   g_wt [Dd*FFd];      // transposed fp16 weight [N][K]
__device__ __align__(256) float g_bcat[3*Dd];

__device__ __forceinline__ void split1(float v, f16* h, f16* l, size_t idx) {
    f16 hv = __float2half_rn(v);
    h[idx] = hv;
    l[idx] = __float2half_rn(v - __half2float(hv));
}

// ---------------- weight transpose + fp16 convert: W[K,N] -> Wt[N,K] ----------------
__device__ __forceinline__ void wtcvt_body(const float* __restrict__ W,
                                           f16* __restrict__ t,
                                           int K, int N, int rowOff,
                                           float (*tile)[33]) {
    int kk = blockIdx.y * 32, nn = blockIdx.x * 32;
    int tx = threadIdx.x, ty = threadIdx.y;   // 32 x 8
#pragma unroll
    for (int i = 0; i < 4; i++)
        tile[ty + 8*i][tx] = W[(size_t)(kk + ty + 8*i) * N + nn + tx];
    __syncthreads();
#pragma unroll
    for (int i = 0; i < 4; i++) {
        float v = tile[tx][ty + 8*i];
        t[(size_t)(rowOff + nn + ty + 8*i) * K + kk + tx] = __float2half_rn(v);
    }
}
__global__ void wtcvt_kernel(const float* __restrict__ W, f16* __restrict__ t,
                             int K, int N, int rowOff) {
    __shared__ float tile[32][33];
    wtcvt_body(W, t, K, N, rowOff, tile);
}
__global__ void wtcvt3_kernel(const float* __restrict__ W0, const float* __restrict__ W1,
                              const float* __restrict__ W2, f16* __restrict__ t) {
    __shared__ float tile[32][33];
    const float* W = (blockIdx.z == 0) ? W0 : (blockIdx.z == 1) ? W1 : W2;
    wtcvt_body(W, t, Dd, Dd, blockIdx.z * Dd, tile);
}

// ---------------- bias concat for fused QKV ----------------
__global__ void bcat_kernel(const float* __restrict__ bq, const float* __restrict__ bk,
                            const float* __restrict__ bv, float* __restrict__ o) {
    int i = blockIdx.x * 256 + threadIdx.x;
    if (i < 3*Dd)
        o[i] = (i < Dd) ? bq[i] : ((i < 2*Dd) ? bk[i - Dd] : bv[i - 2*Dd]);
}

// ---------------- layernorm (fused fp16 split output) ----------------
__global__ void ln_split_kernel(const float* __restrict__ x,
                                const float* __restrict__ g,
                                const float* __restrict__ b,
                                f16* __restrict__ oh, f16* __restrict__ ol) {
    int row = blockIdx.x;
    const float* xr = x + (size_t)row * Dd;
    int tid = threadIdx.x;                 // 256 threads
    int lane = tid & 31, warp = tid >> 5;
    __shared__ float red[32];

    float lv[4]; float s = 0.f;
#pragma unroll
    for (int i = 0; i < 4; i++) { lv[i] = xr[tid + i*256]; s += lv[i]; }
#pragma unroll
    for (int off = 16; off; off >>= 1) s += __shfl_down_sync(0xffffffffu, s, off);
    if (lane == 0) red[warp] = s;
    __syncthreads();
    if (tid == 0) { float t = 0.f; for (int w = 0; w < 8; w++) t += red[w]; red[0] = t; }
    __syncthreads();
    float mu = red[0] * (1.0f / Dd);
    __syncthreads();

    float vs = 0.f;
#pragma unroll
    for (int i = 0; i < 4; i++) { float d = lv[i] - mu; vs += d * d; }
#pragma unroll
    for (int off = 16; off; off >>= 1) vs += __shfl_down_sync(0xffffffffu, vs, off);
    if (lane == 0) red[warp] = vs;
    __syncthreads();
    if (tid == 0) { float t = 0.f; for (int w = 0; w < 8; w++) t += red[w]; red[0] = t; }
    __syncthreads();
    float inv = rsqrtf(red[0] * (1.0f / Dd) + 1e-5f);

#pragma unroll
    for (int i = 0; i < 4; i++) {
        int c = tid + i * 256;
        float v = (lv[i] - mu) * inv * g[c] + b[c];
        split1(v, oh, ol, (size_t)row * Dd + c);
    }
}

// ---------------- HMMA fp16 GEMM: BM=BN=128, 4 warps of 64x64, 2 CTA/SM -------------
// AT = number of A terms (1: C = A@B^T ; 2: C = (Ah+Al)@B^T)
#define RS 80
#define ARR (128*RS)                // 10240 B per array
#define NSTAGE 3
#define GEMM_SMEM_MAX (NSTAGE*3*ARR)   // 92160 (AT=2 case)

__device__ __forceinline__ void cp16(uint32_t s, const void* g) {
    asm volatile("cp.async.cg.shared.global [%0], [%1], 16;" :: "r"(s), "l"(g) : "memory");
}
#define LDSM4(r, a) asm volatile( \
    "ldmatrix.sync.aligned.m8n8.x4.shared.b16 {%0,%1,%2,%3}, [%4];" \
    : "=r"((r)[0]), "=r"((r)[1]), "=r"((r)[2]), "=r"((r)[3]) : "r"(a))
#define MMA_OP(d, a, b0, b1) asm volatile( \
    "mma.sync.aligned.m16n8k16.row.col.f32.f16.f16.f32 " \
    "{%0,%1,%2,%3}, {%4,%5,%6,%7}, {%8,%9}, {%0,%1,%2,%3};\n" \
    : "+f"((d)[0]), "+f"((d)[1]), "+f"((d)[2]), "+f"((d)[3]) \
    : "r"((a)[0]), "r"((a)[1]), "r"((a)[2]), "r"((a)[3]), "r"(b0), "r"(b1))

template<int AT, bool DO_GELU, bool DO_RES, bool OUTH>
__global__ __launch_bounds__(128, 2)
void bgemm_mma(const f16* __restrict__ Ah, const f16* __restrict__ Al,
               const f16* __restrict__ B,
               const float* __restrict__ bias, const float* __restrict__ res,
               float* __restrict__ C, f16* __restrict__ Ch,
               int M, int N, int K) {
    extern __shared__ __align__(128) char smem[];
    const int STG = (AT + 1) * ARR;
    const int tid = threadIdx.x, lane = tid & 31, warp = tid >> 5;
    const int wm = warp >> 1, wn = warp & 1;   // 2 x 2, warp tile 64x64
    const int rowBase = blockIdx.y * 128, colBase = blockIdx.x * 128;
    const uint32_t sb = (uint32_t)__cvta_generic_to_shared(smem);
    const int NS = K >> 5;

    auto issue = [&](int s) {
        uint32_t st = sb + (uint32_t)(s % 3) * STG;
        int kk = s << 5;
#pragma unroll
        for (int j = 0; j < 4; j++) {
            int c = tid + (j << 7);               // 0..511
            int r = c >> 2, ke = (c & 3) << 3;
            uint32_t dst = st + r * RS + ((c & 3) << 4);
            size_t ga = (size_t)(rowBase + r) * K + kk + ke;
            size_t gb = (size_t)(colBase + r) * K + kk + ke;
            cp16(dst, Ah + ga);
            if (AT == 2) cp16(dst + ARR, Al + ga);
            cp16(dst + AT*ARR, B + gb);
        }
        asm volatile("cp.async.commit_group;" ::: "memory");
    };

    float acc[4][8][4] = {};   // [mi][n8][4]

    issue(0); issue(1); issue(2);

    for (int s = 0; s < NS; s++) {
        int rem = NS - 1 - s;
        if (rem >= 2)      asm volatile("cp.async.wait_group 2;" ::: "memory");
        else if (rem == 1) asm volatile("cp.async.wait_group 1;" ::: "memory");
        else               asm volatile("cp.async.wait_group 0;" ::: "memory");
        __syncthreads();

        uint32_t st = sb + (uint32_t)(s % 3) * STG;
        uint32_t aBase = st + (wm * 64 + (lane & 15)) * RS + ((lane >> 4) << 4);
        uint32_t bBase = st + AT*ARR + (wn * 64 + (lane & 15)) * RS + ((lane >> 4) << 4);
#pragma unroll
        for (int ks = 0; ks < 2; ks++) {
            uint32_t ko = ks * 32;
            uint32_t ah[4][4], alr[4][4], bh[4][4];
#pragma unroll
            for (int mi = 0; mi < 4; mi++) {
                LDSM4(ah[mi], aBase + mi * (16*RS) + ko);
                if (AT == 2) LDSM4(alr[mi], aBase + ARR + mi * (16*RS) + ko);
            }
#pragma unroll
            for (int nb = 0; nb < 4; nb++)
                LDSM4(bh[nb], bBase + nb * (16*RS) + ko);
#pragma unroll
            for (int mi = 0; mi < 4; mi++)
#pragma unroll
                for (int nb = 0; nb < 4; nb++)
#pragma unroll
                    for (int g = 0; g < 2; g++) {
                        float* d = acc[mi][nb*2 + g];
                        MMA_OP(d, ah[mi], bh[nb][g], bh[nb][g+2]);
                        if (AT == 2) MMA_OP(d, alr[mi], bh[nb][g], bh[nb][g+2]);
                    }
        }
        __syncthreads();
        if (s + 3 < NS) issue(s + 3);
    }

    // ---- epilogue ----
#pragma unroll
    for (int mi = 0; mi < 4; mi++) {
        int r0 = rowBase + wm * 64 + mi * 16 + (lane >> 2);
#pragma unroll
        for (int n8 = 0; n8 < 8; n8++) {
            int c = colBase + wn * 64 + (n8 >> 1) * 16 + (n8 & 1) * 8 + (lane & 3) * 2;
            float* d = acc[mi][n8];
            float b0 = bias[c], b1 = bias[c + 1];
#pragma unroll
            for (int p = 0; p < 2; p++) {
                int r = r0 + p * 8;
                float v0 = d[p*2]     + b0;
                float v1 = d[p*2 + 1] + b1;
                if (DO_GELU) {
                    v0 = 0.5f * v0 * (1.0f + erff(v0 * 0.70710678118654752f));
                    v1 = 0.5f * v1 * (1.0f + erff(v1 * 0.70710678118654752f));
                }
                if (DO_RES) {
                    float2 rr = *(const float2*)(res + (size_t)r * N + c);
                    v0 += rr.x; v1 += rr.y;
                }
                if (OUTH) {
                    f16 h0 = __float2half_rn(v0), h1 = __float2half_rn(v1);
                    uint32_t hp = ((uint32_t)*(uint16_t*)&h1 << 16) | *(uint16_t*)&h0;
                    *(uint32_t*)(Ch + (size_t)r * N + c) = hp;
                } else {
                    *(float2*)(C + (size_t)r * N + c) = make_float2(v0, v1);
                }
            }
        }
    }
}

// ---------------- query-tile flash sparse attention (hi-only output) -----------------
#define KST 68
#define PST 130
#define ATT_SMEM ((2*128*KST + 128*PST) * 4)   // 136192 B

__global__ __launch_bounds__(256)
void attn2_kernel(const float* __restrict__ qkv, const int* __restrict__ mask,
                  f16* __restrict__ oh) {
    extern __shared__ float sm[];
    float* Ks = sm;
    float* Vs = sm + 128*KST;
    float* Ps = sm + 2*128*KST;

    const int qb = blockIdx.x, h = blockIdx.y, b = blockIdx.z;
    const int tid = threadIdx.x;
    const int qi = tid >> 1, half = tid & 1;
    const int i = qb * 128 + qi;
    const float scale = 0.125f;
    const int* mrow = mask + (size_t)i * Ss;

    float qreg[64];
    {
        const float* qptr = qkv + ((size_t)b * Ss + i) * (3*Dd) + h * DK;
#pragma unroll
        for (int d4 = 0; d4 < 16; d4++) {
            float4 v = *(const float4*)(qptr + 4*d4);
            qreg[4*d4] = v.x; qreg[4*d4+1] = v.y; qreg[4*d4+2] = v.z; qreg[4*d4+3] = v.w;
        }
    }

    float m = -3.0e38f, l = 0.f;
    float o[32];
#pragma unroll
    for (int d = 0; d < 32; d++) o[d] = 0.f;

    for (int mm = 2; mm <= qb; mm++) {
        int j = i - 128 * mm;
        const float* kr = qkv + ((size_t)b * Ss + j) * (3*Dd) + Dd + h * DK + half * 32;
        float s0 = 0, s1 = 0, s2 = 0, s3 = 0;
#pragma unroll
        for (int d4 = 0; d4 < 8; d4++) {
            float4 kv = *(const float4*)(kr + 4*d4);
            s0 += qreg[half*32 + 4*d4]     * kv.x;
            s1 += qreg[half*32 + 4*d4 + 1] * kv.y;
            s2 += qreg[half*32 + 4*d4 + 2] * kv.z;
            s3 += qreg[half*32 + 4*d4 + 3] * kv.w;
        }
        float sc = (s0 + s1) + (s2 + s3);
        sc += __shfl_xor_sync(0xffffffffu, sc, 1);
        sc *= scale;
        if (mrow[j] == 0) sc = NEGV;

        float mn = fmaxf(m, sc);
        float corr = __expf(m - mn);
        float p = __expf(sc - mn);
        l = l * corr + (half ? 0.f : p);
        m = mn;
        const float* vr = qkv + ((size_t)b * Ss + j) * (3*Dd) + 2*Dd + h * DK + half * 32;
#pragma unroll
        for (int d4 = 0; d4 < 8; d4++) {
            float4 vv = *(const float4*)(vr + 4*d4);
            o[4*d4]   = o[4*d4]   * corr + p * vv.x;
            o[4*d4+1] = o[4*d4+1] * corr + p * vv.y;
            o[4*d4+2] = o[4*d4+2] * corr + p * vv.z;
            o[4*d4+3] = o[4*d4+3] * corr + p * vv.w;
        }
    }

    int t0 = (qb > 0) ? qb - 1 : 0;
    for (int t = t0; t <= qb; t++) {
        __syncthreads();
        const float* gk = qkv + ((size_t)b * Ss + t*128) * (3*Dd) + Dd + h * DK;
        const float* gv = gk + Dd;
        for (int idx = tid; idx < 8192; idx += 256) {
            int r = idx >> 6, d = idx & 63;
            Ks[r*KST + d] = gk[(size_t)r * (3*Dd) + d];
            Vs[r*KST + d] = gv[(size_t)r * (3*Dd) + d];
        }
        __syncthreads();

        float tmax = -3.0e38f;
        int jbase = t * 128;
        for (int c = 0; c < 64; c++) {
            int kj = half*64 + c;
            bool allowed = (t == qb) ? (kj <= qi) : (kj >= qi);
            float sc = NEGV;
            if (allowed && mrow[jbase + kj] != 0) {
                const float* kr = &Ks[kj*KST];
                float s0 = 0, s1 = 0, s2 = 0, s3 = 0;
#pragma unroll
                for (int d4 = 0; d4 < 16; d4++) {
                    float4 kv = *(const float4*)(kr + 4*d4);
                    s0 += qreg[4*d4]   * kv.x;
                    s1 += qreg[4*d4+1] * kv.y;
                    s2 += qreg[4*d4+2] * kv.z;
                    s3 += qreg[4*d4+3] * kv.w;
                }
                sc = ((s0 + s1) + (s2 + s3)) * scale;
            }
            Ps[qi*PST + kj] = sc;
            tmax = fmaxf(tmax, sc);
        }
        tmax = fmaxf(tmax, __shfl_xor_sync(0xffffffffu, tmax, 1));
        float mn = fmaxf(m, tmax);
        float corr = __expf(m - mn);
        float lsum = 0.f;
        for (int c = 0; c < 64; c++) {
            int kj = half*64 + c;
            float p = __expf(Ps[qi*PST + kj] - mn);
            Ps[qi*PST + kj] = p;
            lsum += p;
        }
        l = l * corr + lsum;
        m = mn;
#pragma unroll
        for (int d = 0; d < 32; d++) o[d] *= corr;
        __syncthreads();

        for (int kj = 0; kj < 128; kj++) {
            float p = Ps[qi*PST + kj];
            if (p != 0.f) {
                const float* vr = &Vs[kj*KST + half*32];
#pragma unroll
                for (int d4 = 0; d4 < 8; d4++) {
                    float4 vv = *(const float4*)(vr + 4*d4);
                    o[4*d4]   += p * vv.x;
                    o[4*d4+1] += p * vv.y;
                    o[4*d4+2] += p * vv.z;
                    o[4*d4+3] += p * vv.w;
                }
            }
        }
    }

    float lt = l + __shfl_xor_sync(0xffffffffu, l, 1);
    float inv = 1.0f / lt;
    size_t obase = ((size_t)b * Ss + i) * Dd + h * DK + half * 32;
#pragma unroll
    for (int d = 0; d < 32; d++)
        oh[obase + d] = __float2half_rn(o[d] * inv);
}

// ---------------- launch ----------------
extern "C" void kernel_launch(void* const* d_in, const int* in_sizes, int n_in,
                              void* d_out, int out_size) {
    const float* x   = (const float*)d_in[0];
    const int*   msk = (const int*)  d_in[1];
    const float* Wq  = (const float*)d_in[2],  *bq  = (const float*)d_in[3];
    const float* Wk  = (const float*)d_in[4],  *bk  = (const float*)d_in[5];
    const float* Wv  = (const float*)d_in[6],  *bv  = (const float*)d_in[7];
    const float* Wo  = (const float*)d_in[8],  *bo  = (const float*)d_in[9];
    const float* W1  = (const float*)d_in[10], *bf1 = (const float*)d_in[11];
    const float* W2  = (const float*)d_in[12], *bf2 = (const float*)d_in[13];
    const float* g1  = (const float*)d_in[14], *bl1 = (const float*)d_in[15];
    const float* g2  = (const float*)d_in[16], *bl2 = (const float*)d_in[17];
    float* out = (float*)d_out;

    float *qkv_, *x1_, *bcat_;
    f16 *sah, *sal, *sfh, *wt;
    cudaGetSymbolAddress((void**)&qkv_, g_qkv);
    cudaGetSymbolAddress((void**)&x1_,  g_x1);
    cudaGetSymbolAddress((void**)&bcat_,g_bcat);
    cudaGetSymbolAddress((void**)&sah,  g_sa_h);
    cudaGetSymbolAddress((void**)&sal,  g_sa_l);
    cudaGetSymbolAddress((void**)&sfh,  g_sf_h);
    cudaGetSymbolAddress((void**)&wt,   g_wt);

    cudaFuncSetAttribute(bgemm_mma<2, false, false, false>,
                         cudaFuncAttributeMaxDynamicSharedMemorySize, GEMM_SMEM_MAX);
    cudaFuncSetAttribute(bgemm_mma<1, false, true, false>,
                         cudaFuncAttributeMaxDynamicSharedMemorySize, GEMM_SMEM_MAX);
    cudaFuncSetAttribute(bgemm_mma<2, true, false, true>,
                         cudaFuncAttributeMaxDynamicSharedMemorySize, GEMM_SMEM_MAX);
    cudaFuncSetAttribute(attn2_kernel,
                         cudaFuncAttributeMaxDynamicSharedMemorySize, ATT_SMEM);

    dim3 wblk(32, 8);

    // pre-LN 1 -> split(n)
    ln_split_kernel<<<ROWS, 256>>>(x, g1, bl1, sah, sal);

    // fused QKV (2-term A)
    bcat_kernel<<<12, 256>>>(bq, bk, bv, bcat_);
    wtcvt3_kernel<<<dim3(Dd/32, Dd/32, 3), wblk>>>(Wq, Wk, Wv, wt);
    bgemm_mma<2, false, false, false><<<dim3(3*Dd/128, ROWS/128), 128, NSTAGE*3*ARR>>>(
        sah, sal, wt, bcat_, nullptr, qkv_, nullptr, ROWS, 3*Dd, Dd);

    // sparse flash attention -> o (hi only, overwrites sah)
    attn2_kernel<<<dim3(Ss/128, Hh, Bb), 256, ATT_SMEM>>>(qkv_, msk, sah);

    // output projection + residual -> x1 (1-term A)
    wtcvt_kernel<<<dim3(Dd/32, Dd/32), wblk>>>(Wo, wt, Dd, Dd, 0);
    bgemm_mma<1, false, true, false><<<dim3(Dd/128, ROWS/128), 128, NSTAGE*2*ARR>>>(
        sah, nullptr, wt, bo, x, x1_, nullptr, ROWS, Dd, Dd);

    // pre-LN 2 -> split(n2)
    ln_split_kernel<<<ROWS, 256>>>(x1_, g2, bl2, sah, sal);

    // FFN up + GELU -> ff (hi only; 2-term A)
    wtcvt_kernel<<<dim3(FFd/32, Dd/32), wblk>>>(W1, wt, Dd, FFd, 0);
    bgemm_mma<2, true, false, true><<<dim3(FFd/128, ROWS/128), 128, NSTAGE*3*ARR>>>(
        sah, sal, wt, bf1, nullptr, nullptr, sfh, ROWS, FFd, Dd);

    // FFN down + residual -> out (1-term A)
    wtcvt_kernel<<<dim3(Dd/32, FFd/32), wblk>>>(W2, wt, FFd, Dd, 0);
    bgemm_mma<1, false, true, false><<<dim3(Dd/128, ROWS/128), 128, NSTAGE*2*ARR>>>(
        sfh, nullptr, wt, bf2, x1_, out, nullptr, ROWS, Dd, FFd);
}